// round 1
// baseline (speedup 1.0000x reference)
#include <cuda_runtime.h>
#include <cuda_bf16.h>
#include <cstdint>

// SigmaModel: x=[s,a](40) -> relu GEMM1 (64) -> GEMM2 (528 tri values)
// -> symmetric 32x32 with exp() diagonal.  B = 131072, out fp32 [B,32,32].
//
// Strategy: f32x2 packed FMAs over output-index pairs (t, t+1).
//  - h[k] computed scalar, splatted once into packed (h,h) regs (64 x u64).
//  - W2 staged in smem interleaved as pairs (W2[t][k], W2[t+1][k]) so one
//    LDS.128 feeds two fma.rn.f32x2.
//  - triu (i,j) -> linear output offsets precomputed in a smem LUT.

#define BATCH   131072
#define DIM     32
#define ADIM    8
#define INDIM   40
#define HID     64
#define TRI     528
#define TPAIRS  264
#define NTHR    256

// smem layout (floats):
//  [0, 33792)           W2 pair-interleaved: pair (tp,k) at tp*128 + 2k {+0:t0, +1:t1}
//  [33792, 36352)       W1 row-major [64][40]
//  [36352, 36416)       b1
//  [36416, 36944)       b2
//  then 528 ushort2 LUT: (i*32+j, j*32+i)
#define SM_W2_F   0
#define SM_W1_F   33792
#define SM_B1_F   36352
#define SM_B2_F   36416
#define SM_FLOATS 36944
#define SM_BYTES  (SM_FLOATS * 4 + TRI * 4)

__device__ __forceinline__ unsigned long long pack2(float lo, float hi) {
    unsigned long long p;
    asm("mov.b64 %0, {%1, %2};" : "=l"(p) : "f"(lo), "f"(hi));
    return p;
}
__device__ __forceinline__ void unpack2(unsigned long long p, float& lo, float& hi) {
    asm("mov.b64 {%0, %1}, %2;" : "=f"(lo), "=f"(hi) : "l"(p));
}
__device__ __forceinline__ unsigned long long fma2(unsigned long long a,
                                                   unsigned long long b,
                                                   unsigned long long c) {
    unsigned long long d;
    asm("fma.rn.f32x2 %0, %1, %2, %3;" : "=l"(d) : "l"(a), "l"(b), "l"(c));
    return d;
}
__device__ __forceinline__ unsigned long long add2(unsigned long long a,
                                                   unsigned long long b) {
    unsigned long long d;
    asm("add.rn.f32x2 %0, %1, %2;" : "=l"(d) : "l"(a), "l"(b));
    return d;
}

__global__ void __launch_bounds__(NTHR, 1)
sigma_kernel(const float* __restrict__ s,
             const float* __restrict__ a,
             const float* __restrict__ W1,
             const float* __restrict__ b1,
             const float* __restrict__ W2,
             const float* __restrict__ b2,
             float* __restrict__ out)
{
    extern __shared__ float smf[];
    float*    sm_w2  = smf + SM_W2_F;
    float*    sm_W1  = smf + SM_W1_F;
    float*    sm_b1  = smf + SM_B1_F;
    float*    sm_b2  = smf + SM_B2_F;
    ushort2*  sm_off = (ushort2*)(smf + SM_FLOATS);

    const int tid = threadIdx.x;

    // ---- stage weights into smem ----
    for (int idx = tid; idx < TRI * HID; idx += NTHR) {
        int t = idx >> 6, k = idx & 63;
        sm_w2[(t >> 1) * 128 + k * 2 + (t & 1)] = W2[idx];
    }
    for (int idx = tid; idx < HID * INDIM; idx += NTHR) sm_W1[idx] = W1[idx];
    if (tid < HID) sm_b1[tid] = b1[tid];
    for (int t = tid; t < TRI; t += NTHR) {
        sm_b2[t] = b2[t];
        int i = 0, rem = t;
        while (rem >= DIM - i) { rem -= DIM - i; ++i; }
        int j = i + rem;
        sm_off[t] = make_ushort2((unsigned short)(i * DIM + j),
                                 (unsigned short)(j * DIM + i));
    }
    __syncthreads();

    const int g      = blockIdx.x * NTHR + tid;
    const int stride = gridDim.x * NTHR;

    for (int e = g; e < BATCH; e += stride) {
        // ---- load x = [s(32), a(8)] ----
        float x[INDIM];
        const float4* sv = reinterpret_cast<const float4*>(s + (size_t)e * DIM);
        #pragma unroll
        for (int q = 0; q < 8; ++q) {
            float4 v = sv[q];
            x[4*q+0] = v.x; x[4*q+1] = v.y; x[4*q+2] = v.z; x[4*q+3] = v.w;
        }
        const float4* av = reinterpret_cast<const float4*>(a + (size_t)e * ADIM);
        #pragma unroll
        for (int q = 0; q < 2; ++q) {
            float4 v = av[q];
            x[32+4*q+0] = v.x; x[32+4*q+1] = v.y; x[32+4*q+2] = v.z; x[32+4*q+3] = v.w;
        }

        // ---- layer 1: h = relu(W1 x + b1), splat into packed (h,h) ----
        unsigned long long hs[HID];
        #pragma unroll
        for (int i = 0; i < HID; ++i) {
            float acc = sm_b1[i];
            const float4* w = reinterpret_cast<const float4*>(sm_W1 + i * INDIM);
            #pragma unroll
            for (int q = 0; q < 10; ++q) {
                float4 wv = w[q];
                acc = fmaf(x[4*q+0], wv.x, acc);
                acc = fmaf(x[4*q+1], wv.y, acc);
                acc = fmaf(x[4*q+2], wv.z, acc);
                acc = fmaf(x[4*q+3], wv.w, acc);
            }
            float v = fmaxf(acc, 0.0f);
            hs[i] = pack2(v, v);
        }

        // ---- layer 2 + scatter ----
        float* oe = out + (size_t)e * (DIM * DIM);
        const ulonglong2* w2q = reinterpret_cast<const ulonglong2*>(sm_w2);

        #pragma unroll 2
        for (int tp = 0; tp < TPAIRS; ++tp) {
            const ulonglong2* wrow = w2q + tp * 32;
            unsigned long long acc0 = pack2(sm_b2[2*tp], sm_b2[2*tp+1]);
            unsigned long long acc1 = 0ull, acc2 = 0ull, acc3 = 0ull;
            #pragma unroll
            for (int m = 0; m < 32; m += 2) {
                ulonglong2 w01 = wrow[m];
                ulonglong2 w23 = wrow[m+1];
                acc0 = fma2(hs[2*m+0], w01.x, acc0);
                acc1 = fma2(hs[2*m+1], w01.y, acc1);
                acc2 = fma2(hs[2*m+2], w23.x, acc2);
                acc3 = fma2(hs[2*m+3], w23.y, acc3);
            }
            unsigned long long accv = add2(add2(acc0, acc2), add2(acc1, acc3));
            float v0, v1;
            unpack2(accv, v0, v1);

            ushort2 o0 = sm_off[2*tp];
            ushort2 o1 = sm_off[2*tp+1];
            if (o0.x == o0.y) oe[o0.x] = __expf(v0);
            else { oe[o0.x] = v0; oe[o0.y] = v0; }
            if (o1.x == o1.y) oe[o1.x] = __expf(v1);
            else { oe[o1.x] = v1; oe[o1.y] = v1; }
        }
    }
}

extern "C" void kernel_launch(void* const* d_in, const int* in_sizes, int n_in,
                              void* d_out, int out_size)
{
    const float* s  = (const float*)d_in[0];
    const float* a  = (const float*)d_in[1];
    const float* W1 = (const float*)d_in[2];
    const float* b1 = (const float*)d_in[3];
    const float* W2 = (const float*)d_in[4];
    const float* b2 = (const float*)d_in[5];
    float* out = (float*)d_out;

    int nsm = 148;
    cudaDeviceGetAttribute(&nsm, cudaDevAttrMultiProcessorCount, 0);

    cudaFuncSetAttribute(sigma_kernel,
                         cudaFuncAttributeMaxDynamicSharedMemorySize, SM_BYTES);

    sigma_kernel<<<nsm, NTHR, SM_BYTES>>>(s, a, W1, b1, W2, b2, out);
}

// round 2
// speedup vs baseline: 2.6659x; 2.6659x over previous
#include <cuda_runtime.h>
#include <cuda_bf16.h>
#include <cstdint>

// SigmaModel: x=[s,a](40) -> relu GEMM1 (64) -> GEMM2 (528 tri) -> symmetric
// 32x32 with exp() diagonal. B = 131072, out fp32 [B,32,32].
//
// Design (R1): persistent-weight, warp-specialized block.
//  - 608 threads. Threads 64..591: each owns ONE tri output t, holding its 64
//    W2 weights as 32 packed u64 in REGISTERS for the entire kernel.
//  - Threads 0..63: layer-1 (one h each, W1 from padded smem).
//  - Per element: output thread does 32 fma.rn.f32x2 (k-pair packing) +
//    16 broadcast LDS.128 of h. Results staged in smem.
//  - Store phase: dense assembly via LUT, row-contiguous coalesced STG.32.
//  - E=4 elements per barrier phase.

#define BATCH   131072
#define DIM     32
#define ADIM    8
#define INDIM   40
#define HID     64
#define TRI     528
#define NTHR    608
#define E       4
#define W1S     41   // padded row stride for conflict-free W1 smem

__device__ __forceinline__ unsigned long long pack2(float lo, float hi) {
    unsigned long long p;
    asm("mov.b64 %0, {%1, %2};" : "=l"(p) : "f"(lo), "f"(hi));
    return p;
}
__device__ __forceinline__ void unpack2(unsigned long long p, float& lo, float& hi) {
    asm("mov.b64 {%0, %1}, %2;" : "=f"(lo), "=f"(hi) : "l"(p));
}
__device__ __forceinline__ unsigned long long fma2(unsigned long long a,
                                                   unsigned long long b,
                                                   unsigned long long c) {
    unsigned long long d;
    asm("fma.rn.f32x2 %0, %1, %2, %3;" : "=l"(d) : "l"(a), "l"(b), "l"(c));
    return d;
}

__global__ void __launch_bounds__(NTHR, 1)
sigma_kernel(const float* __restrict__ s,
             const float* __restrict__ a,
             const float* __restrict__ W1,
             const float* __restrict__ b1,
             const float* __restrict__ W2,
             const float* __restrict__ b2,
             float* __restrict__ out)
{
    __shared__ float          x_sm[E][INDIM];
    __shared__ float          h_sm[E][HID];
    __shared__ float          stage[E][TRI];
    __shared__ float          w1_sm[HID * W1S];
    __shared__ unsigned short lut[DIM * DIM];

    const int tid  = threadIdx.x;
    const int wid  = tid >> 5;
    const int lane = tid & 31;

    // ---- one-time setup ----
    // dense (i,j) -> tri index LUT
    for (int idx = tid; idx < DIM * DIM; idx += NTHR) {
        int i = idx >> 5, j = idx & 31;
        int ii = min(i, j), jj = max(i, j);
        lut[idx] = (unsigned short)(ii * (2 * DIM + 1 - ii) / 2 + (jj - ii));
    }
    // W1 into padded smem
    for (int idx = tid; idx < HID * INDIM; idx += NTHR) {
        int r = idx / INDIM, c = idx % INDIM;
        w1_sm[r * W1S + c] = W1[idx];
    }

    const bool is_l1 = (tid < HID);
    float b1r = is_l1 ? b1[tid] : 0.0f;

    const int  t_out = tid - HID;
    const bool is_p2 = (t_out >= 0) && (t_out < TRI);
    unsigned long long w2r[32];
    float b2r = 0.0f;
    if (is_p2) {
        const ulonglong2* wrow = reinterpret_cast<const ulonglong2*>(W2 + (size_t)t_out * HID);
        #pragma unroll
        for (int q = 0; q < 16; ++q) {
            ulonglong2 v = wrow[q];
            w2r[2 * q]     = v.x;
            w2r[2 * q + 1] = v.y;
        }
        b2r = b2[t_out];
    }
    __syncthreads();

    // ---- main loop over element groups ----
    for (int base = blockIdx.x * E; base < BATCH; base += gridDim.x * E) {
        // stage x = [s(32), a(8)] for E elements
        if (tid < E * INDIM) {
            int e = tid / INDIM, k = tid - e * INDIM;
            int eg = base + e;
            x_sm[e][k] = (k < DIM) ? s[(size_t)eg * DIM + k]
                                   : a[(size_t)eg * ADIM + (k - DIM)];
        }
        __syncthreads();

        // layer 1: h = relu(W1 x + b1)
        if (is_l1) {
            #pragma unroll
            for (int e = 0; e < E; ++e) {
                float xr[INDIM];
                #pragma unroll
                for (int q = 0; q < 10; ++q) {
                    float4 xv = reinterpret_cast<const float4*>(x_sm[e])[q];
                    xr[4*q+0] = xv.x; xr[4*q+1] = xv.y;
                    xr[4*q+2] = xv.z; xr[4*q+3] = xv.w;
                }
                float acc = b1r;
                #pragma unroll
                for (int k = 0; k < INDIM; ++k)
                    acc = fmaf(w1_sm[tid * W1S + k], xr[k], acc);
                h_sm[e][tid] = fmaxf(acc, 0.0f);
            }
        }
        __syncthreads();

        // layer 2: each output thread, 32 fma2 per element, weights in regs
        if (is_p2) {
            unsigned long long acc[E];
            #pragma unroll
            for (int e = 0; e < E; ++e) acc[e] = pack2(b2r, 0.0f);
            #pragma unroll
            for (int q = 0; q < 16; ++q) {
                #pragma unroll
                for (int e = 0; e < E; ++e) {
                    ulonglong2 h2 = reinterpret_cast<const ulonglong2*>(h_sm[e])[q];
                    acc[e] = fma2(w2r[2 * q],     h2.x, acc[e]);
                    acc[e] = fma2(w2r[2 * q + 1], h2.y, acc[e]);
                }
            }
            #pragma unroll
            for (int e = 0; e < E; ++e) {
                float lo, hi;
                unpack2(acc[e], lo, hi);
                stage[e][t_out] = lo + hi;
            }
        }
        __syncthreads();

        // store: dense assembly, coalesced rows. 16 tasks = (e, 8-row block)
        if (wid < 16) {
            int e  = wid >> 2;
            int rb = (wid & 3) * 8;
            float* oe = out + (size_t)(base + e) * (DIM * DIM);
            #pragma unroll
            for (int r = 0; r < 8; ++r) {
                int i = rb + r;
                int t = lut[i * DIM + lane];
                float v = stage[e][t];
                if (lane == i) v = __expf(v);
                oe[i * DIM + lane] = v;
            }
        }
        __syncthreads();
    }
}

extern "C" void kernel_launch(void* const* d_in, const int* in_sizes, int n_in,
                              void* d_out, int out_size)
{
    const float* s  = (const float*)d_in[0];
    const float* a  = (const float*)d_in[1];
    const float* W1 = (const float*)d_in[2];
    const float* b1 = (const float*)d_in[3];
    const float* W2 = (const float*)d_in[4];
    const float* b2 = (const float*)d_in[5];
    float* out = (float*)d_out;

    int nsm = 148;
    cudaDeviceGetAttribute(&nsm, cudaDevAttrMultiProcessorCount, 0);

    sigma_kernel<<<nsm, NTHR>>>(s, a, W1, b1, W2, b2, out);
}